// round 2
// baseline (speedup 1.0000x reference)
#include <cuda_runtime.h>
#include <cuda_bf16.h>

// ScaledSum pyramid: out = (x + sum_{w in {8,16,32,64,128,256,512}} blockmean_w(x)) / 8
// B=8, H=W=512, C=32 (fp32). softmax over size-1 axis == 1, so 'a' is ignored.
//
// Every pooled term is piecewise-constant on 8x8 blocks -> precompute fused
// pyramid P[B,64,64,C] (4MB), then out = (x + P[block]) * 0.125.
//
// Traffic floor: read x (256MB) + read x (256MB) + write out (256MB) = 768MB.

#define BATCH   8
#define HW      512
#define C4      8            // float4 groups per pixel (C=32)
#define BLK     64           // 8x8 blocks per dim
#define NBLK    (BLK*BLK)    // 4096 blocks per image

// scratch: block-8 sums and fused pyramid, layout [b][by][bx][c4] as float4
__device__ float4 g_S8[BATCH * NBLK * C4];
__device__ float4 g_P [BATCH * NBLK * C4];

static __device__ __forceinline__ float4 f4add(float4 a, float4 b) {
    return make_float4(a.x + b.x, a.y + b.y, a.z + b.z, a.w + b.w);
}
static __device__ __forceinline__ float4 f4fma(float4 a, float s, float4 acc) {
    acc.x += a.x * s; acc.y += a.y * s; acc.z += a.z * s; acc.w += a.w * s;
    return acc;
}

// ---------------------------------------------------------------------------
// Kernel A: per-8x8-block channel sums. One WARP per block; shfl reduction,
// no smem, no barriers. 4096 CTAs x 256 threads.
// ---------------------------------------------------------------------------
__global__ void __launch_bounds__(256) block8_sum_kernel(const float4* __restrict__ x) {
    const int blk  = blockIdx.x * 8 + (threadIdx.x >> 5);   // 0..32767
    const int lane = threadIdx.x & 31;
    const int bx   = blk & 63;
    const int by   = (blk >> 6) & 63;
    const int b    = blk >> 12;

    // float4 base of block's row 0: pixels are C4 float4 each
    const float4* base = x + (size_t)(((b * HW) + by * 8) * HW + bx * 8) * C4;

    float4 acc = make_float4(0.f, 0.f, 0.f, 0.f);
    #pragma unroll
    for (int r = 0; r < 8; r++) {
        const float4* row = base + r * (HW * C4);
        // row holds 8 pixels * 8 c4 = 64 contiguous float4; warp loads 2x512B
        acc = f4add(acc, f4add(row[lane], row[lane + 32]));
    }
    // lanes {c4, c4+8, c4+16, c4+24} share c4 = lane&7 -> butterfly over 8,16
    #pragma unroll
    for (int off = 8; off < 32; off <<= 1) {
        acc.x += __shfl_xor_sync(0xffffffffu, acc.x, off);
        acc.y += __shfl_xor_sync(0xffffffffu, acc.y, off);
        acc.z += __shfl_xor_sync(0xffffffffu, acc.z, off);
        acc.w += __shfl_xor_sync(0xffffffffu, acc.w, off);
    }
    if (lane < 8) g_S8[blk * C4 + lane] = acc;
}

// ---------------------------------------------------------------------------
// Kernel B: build fused pyramid P from S8. One CTA per (b, c4): 64 CTAs.
// smem holds only levels 16..512: 1024+256+64+16+4+1 = 1365 float4 = 21840B.
// S8 is re-read from global in the final fold (L2-resident, trivial).
// ---------------------------------------------------------------------------
__global__ void __launch_bounds__(256) pyramid_kernel() {
    __shared__ float4 l16 [1024];   // [32][32]
    __shared__ float4 l32 [256];    // [16][16]
    __shared__ float4 l64 [64];     // [8][8]
    __shared__ float4 l128[16];     // [4][4]
    __shared__ float4 l256[4];      // [2][2]
    __shared__ float4 l512[1];

    const int b   = blockIdx.x >> 3;
    const int c4  = blockIdx.x & 7;
    const int tid = threadIdx.x;
    const float4* s8g = g_S8 + (size_t)b * NBLK * C4 + c4;  // stride C4

    for (int i = tid; i < 1024; i += 256) {
        int y = i >> 5, x2 = i & 31;
        l16[i] = f4add(f4add(s8g[((2*y  )*64 + 2*x2)*C4], s8g[((2*y  )*64 + 2*x2+1)*C4]),
                       f4add(s8g[((2*y+1)*64 + 2*x2)*C4], s8g[((2*y+1)*64 + 2*x2+1)*C4]));
    }
    __syncthreads();
    {
        int y = tid >> 4, x2 = tid & 15;
        l32[tid] = f4add(f4add(l16[(2*y)*32 + 2*x2],   l16[(2*y)*32 + 2*x2+1]),
                         f4add(l16[(2*y+1)*32 + 2*x2], l16[(2*y+1)*32 + 2*x2+1]));
    }
    __syncthreads();
    if (tid < 64) {
        int y = tid >> 3, x2 = tid & 7;
        l64[tid] = f4add(f4add(l32[(2*y)*16 + 2*x2],   l32[(2*y)*16 + 2*x2+1]),
                         f4add(l32[(2*y+1)*16 + 2*x2], l32[(2*y+1)*16 + 2*x2+1]));
    }
    __syncthreads();
    if (tid < 16) {
        int y = tid >> 2, x2 = tid & 3;
        l128[tid] = f4add(f4add(l64[(2*y)*8 + 2*x2],   l64[(2*y)*8 + 2*x2+1]),
                          f4add(l64[(2*y+1)*8 + 2*x2], l64[(2*y+1)*8 + 2*x2+1]));
    }
    __syncthreads();
    if (tid < 4) {
        int y = tid >> 1, x2 = tid & 1;
        l256[tid] = f4add(f4add(l128[(2*y)*4 + 2*x2],   l128[(2*y)*4 + 2*x2+1]),
                          f4add(l128[(2*y+1)*4 + 2*x2], l128[(2*y+1)*4 + 2*x2+1]));
    }
    __syncthreads();
    if (tid == 0)
        l512[0] = f4add(f4add(l256[0], l256[1]), f4add(l256[2], l256[3]));
    __syncthreads();

    const float i8   = 1.0f / 64.0f;
    const float i16  = 1.0f / 256.0f;
    const float i32  = 1.0f / 1024.0f;
    const float i64  = 1.0f / 4096.0f;
    const float i128 = 1.0f / 16384.0f;
    const float i256 = 1.0f / 65536.0f;
    const float i512 = 1.0f / 262144.0f;

    for (int i = tid; i < NBLK; i += 256) {
        int by = i >> 6, bx = i & 63;
        float4 p = make_float4(0.f, 0.f, 0.f, 0.f);
        p = f4fma(s8g[i * C4],                    i8,   p);
        p = f4fma(l16 [(by>>1)*32 + (bx>>1)],     i16,  p);
        p = f4fma(l32 [(by>>2)*16 + (bx>>2)],     i32,  p);
        p = f4fma(l64 [(by>>3)*8  + (bx>>3)],     i64,  p);
        p = f4fma(l128[(by>>4)*4  + (bx>>4)],     i128, p);
        p = f4fma(l256[(by>>5)*2  + (bx>>5)],     i256, p);
        p = f4fma(l512[0],                        i512, p);
        g_P[((size_t)b * NBLK + i) * C4 + c4] = p;
    }
}

// ---------------------------------------------------------------------------
// Kernel C: out = (x + P[block]) * 0.125, float4-vectorized, coalesced.
// P float4 reused 64x -> L1/L2-resident; within a warp lanes of the same
// pixel-block hit one 128B P line.
// ---------------------------------------------------------------------------
__global__ void __launch_bounds__(256) combine_kernel(const float4* __restrict__ x,
                                                      float4* __restrict__ out,
                                                      int n4) {
    int i = blockIdx.x * blockDim.x + threadIdx.x;
    if (i >= n4) return;

    const int c4  = i & 7;
    const int pix = i >> 3;
    const int w   = pix & 511;
    const int t   = pix >> 9;
    const int h   = t & 511;
    const int b   = t >> 9;

    const int pidx = ((b * BLK + (h >> 3)) * BLK + (w >> 3)) * C4 + c4;

    float4 xv = x[i];
    float4 pv = __ldg(&g_P[pidx]);
    float4 o;
    o.x = (xv.x + pv.x) * 0.125f;
    o.y = (xv.y + pv.y) * 0.125f;
    o.z = (xv.z + pv.z) * 0.125f;
    o.w = (xv.w + pv.w) * 0.125f;
    out[i] = o;
}

// ---------------------------------------------------------------------------
extern "C" void kernel_launch(void* const* d_in, const int* in_sizes, int n_in,
                              void* d_out, int out_size) {
    const float4* x = (const float4*)d_in[0];
    float4* out = (float4*)d_out;

    // A: warp-per-block sums (32768 blocks / 8 warps per CTA)
    block8_sum_kernel<<<BATCH * NBLK / 8, 256>>>(x);

    // B: fused pyramid (static smem only, <48KB)
    pyramid_kernel<<<BATCH * C4, 256>>>();

    // C: elementwise combine
    const int n4 = out_size / 4;   // float4 count = 16,777,216
    combine_kernel<<<(n4 + 255) / 256, 256>>>(x, out, n4);
}

// round 5
// speedup vs baseline: 1.0439x; 1.0439x over previous
#include <cuda_runtime.h>
#include <cuda_bf16.h>

// ScaledSum pyramid: out = (x + sum_{w in {8,16,32,64,128,256,512}} blockmean_w(x)) / 8
// B=8, H=W=512, C=32 (fp32). softmax over size-1 axis == 1, so 'a' is ignored.
//
// Every pooled term is piecewise-constant on 8x8 blocks -> precompute fused
// pyramid P[B,64,64,C] (4MB), then out = (x + P[block]) * 0.125.
//
// Traffic floor: read x (256MB) + read x (256MB) + write out (256MB) = 768MB.

#define BATCH   8
#define HW      512
#define C4      8            // float4 groups per pixel (C=32)
#define BLK     64           // 8x8 blocks per dim
#define NBLK    (BLK*BLK)    // 4096 blocks per image

// scratch: block-8 sums and fused pyramid, layout [b][by][bx][c4] as float4
__device__ float4 g_S8[BATCH * NBLK * C4];
__device__ float4 g_P [BATCH * NBLK * C4];

static __device__ __forceinline__ float4 f4add(float4 a, float4 b) {
    return make_float4(a.x + b.x, a.y + b.y, a.z + b.z, a.w + b.w);
}
static __device__ __forceinline__ float4 f4fma(float4 a, float s, float4 acc) {
    acc.x += a.x * s; acc.y += a.y * s; acc.z += a.z * s; acc.w += a.w * s;
    return acc;
}

// ---------------------------------------------------------------------------
// Kernel A: per-8x8-block channel sums. One WARP per block; shfl reduction,
// no smem, no barriers. 4096 CTAs x 256 threads. Streaming reads (.cs).
// ---------------------------------------------------------------------------
__global__ void __launch_bounds__(256) block8_sum_kernel(const float4* __restrict__ x) {
    const int blk  = blockIdx.x * 8 + (threadIdx.x >> 5);   // 0..32767
    const int lane = threadIdx.x & 31;
    const int bx   = blk & 63;
    const int by   = (blk >> 6) & 63;
    const int b    = blk >> 12;

    // float4 base of block's row 0: pixels are C4 float4 each
    const float4* base = x + (size_t)(((b * HW) + by * 8) * HW + bx * 8) * C4;

    float4 acc = make_float4(0.f, 0.f, 0.f, 0.f);
    #pragma unroll
    for (int r = 0; r < 8; r++) {
        const float4* row = base + r * (HW * C4);
        // row holds 8 pixels * 8 c4 = 64 contiguous float4; warp loads 2x512B
        acc = f4add(acc, f4add(__ldcs(&row[lane]), __ldcs(&row[lane + 32])));
    }
    // lanes {c4, c4+8, c4+16, c4+24} share c4 = lane&7 -> butterfly over 8,16
    #pragma unroll
    for (int off = 8; off < 32; off <<= 1) {
        acc.x += __shfl_xor_sync(0xffffffffu, acc.x, off);
        acc.y += __shfl_xor_sync(0xffffffffu, acc.y, off);
        acc.z += __shfl_xor_sync(0xffffffffu, acc.z, off);
        acc.w += __shfl_xor_sync(0xffffffffu, acc.w, off);
    }
    if (lane < 8) g_S8[blk * C4 + lane] = acc;
}

// ---------------------------------------------------------------------------
// Kernel B: build fused pyramid P from S8. One CTA per (b, c4): 64 CTAs.
// smem holds levels 16..512: 1024+256+64+16+4+1 = 1365 float4 = 21840B.
// ---------------------------------------------------------------------------
__global__ void __launch_bounds__(256) pyramid_kernel() {
    __shared__ float4 l16 [1024];   // [32][32]
    __shared__ float4 l32 [256];    // [16][16]
    __shared__ float4 l64 [64];     // [8][8]
    __shared__ float4 l128[16];     // [4][4]
    __shared__ float4 l256[4];      // [2][2]
    __shared__ float4 l512[1];

    const int b   = blockIdx.x >> 3;
    const int c4  = blockIdx.x & 7;
    const int tid = threadIdx.x;
    const float4* s8g = g_S8 + (size_t)b * NBLK * C4 + c4;  // stride C4

    for (int i = tid; i < 1024; i += 256) {
        int y = i >> 5, x2 = i & 31;
        l16[i] = f4add(f4add(s8g[((2*y  )*64 + 2*x2)*C4], s8g[((2*y  )*64 + 2*x2+1)*C4]),
                       f4add(s8g[((2*y+1)*64 + 2*x2)*C4], s8g[((2*y+1)*64 + 2*x2+1)*C4]));
    }
    __syncthreads();
    {
        int y = tid >> 4, x2 = tid & 15;
        l32[tid] = f4add(f4add(l16[(2*y)*32 + 2*x2],   l16[(2*y)*32 + 2*x2+1]),
                         f4add(l16[(2*y+1)*32 + 2*x2], l16[(2*y+1)*32 + 2*x2+1]));
    }
    __syncthreads();
    if (tid < 64) {
        int y = tid >> 3, x2 = tid & 7;
        l64[tid] = f4add(f4add(l32[(2*y)*16 + 2*x2],   l32[(2*y)*16 + 2*x2+1]),
                         f4add(l32[(2*y+1)*16 + 2*x2], l32[(2*y+1)*16 + 2*x2+1]));
    }
    __syncthreads();
    if (tid < 16) {
        int y = tid >> 2, x2 = tid & 3;
        l128[tid] = f4add(f4add(l64[(2*y)*8 + 2*x2],   l64[(2*y)*8 + 2*x2+1]),
                          f4add(l64[(2*y+1)*8 + 2*x2], l64[(2*y+1)*8 + 2*x2+1]));
    }
    __syncthreads();
    if (tid < 4) {
        int y = tid >> 1, x2 = tid & 1;
        l256[tid] = f4add(f4add(l128[(2*y)*4 + 2*x2],   l128[(2*y)*4 + 2*x2+1]),
                          f4add(l128[(2*y+1)*4 + 2*x2], l128[(2*y+1)*4 + 2*x2+1]));
    }
    __syncthreads();
    if (tid == 0)
        l512[0] = f4add(f4add(l256[0], l256[1]), f4add(l256[2], l256[3]));
    __syncthreads();

    const float i8   = 1.0f / 64.0f;
    const float i16  = 1.0f / 256.0f;
    const float i32  = 1.0f / 1024.0f;
    const float i64  = 1.0f / 4096.0f;
    const float i128 = 1.0f / 16384.0f;
    const float i256 = 1.0f / 65536.0f;
    const float i512 = 1.0f / 262144.0f;

    for (int i = tid; i < NBLK; i += 256) {
        int by = i >> 6, bx = i & 63;
        float4 p = make_float4(0.f, 0.f, 0.f, 0.f);
        p = f4fma(s8g[i * C4],                    i8,   p);
        p = f4fma(l16 [(by>>1)*32 + (bx>>1)],     i16,  p);
        p = f4fma(l32 [(by>>2)*16 + (bx>>2)],     i32,  p);
        p = f4fma(l64 [(by>>3)*8  + (bx>>3)],     i64,  p);
        p = f4fma(l128[(by>>4)*4  + (bx>>4)],     i128, p);
        p = f4fma(l256[(by>>5)*2  + (bx>>5)],     i256, p);
        p = f4fma(l512[0],                        i512, p);
        g_P[((size_t)b * NBLK + i) * C4 + c4] = p;
    }
}

// ---------------------------------------------------------------------------
// Kernel C: out = (x + P[block]) * 0.125, float4-vectorized, 8x coarsened.
// Each thread: 8 independent coalesced load->fma->store chains (MLP ~8).
// x streamed with .cs, out stored with .cs; P cached (.ldg, 64x reuse).
// Grid 8192 CTAs x 256 thr x 8 f4 = 16,777,216 float4 exactly (no bounds).
// ---------------------------------------------------------------------------
#define C_UNROLL 8

__global__ void __launch_bounds__(256) combine_kernel(const float4* __restrict__ x,
                                                      float4* __restrict__ out) {
    const int base = blockIdx.x * (256 * C_UNROLL) + threadIdx.x;

    float4 xv[C_UNROLL];
    int    pidx[C_UNROLL];

    #pragma unroll
    for (int k = 0; k < C_UNROLL; k++) {
        const int i  = base + k * 256;
        xv[k] = __ldcs(&x[i]);
        const int c4  = i & 7;
        const int pix = i >> 3;
        const int w   = pix & 511;
        const int t   = pix >> 9;
        const int h   = t & 511;
        const int b   = t >> 9;
        pidx[k] = ((b * BLK + (h >> 3)) * BLK + (w >> 3)) * C4 + c4;
    }

    #pragma unroll
    for (int k = 0; k < C_UNROLL; k++) {
        const int i = base + k * 256;
        const float4 pv = __ldg(&g_P[pidx[k]]);
        float4 o;
        o.x = (xv[k].x + pv.x) * 0.125f;
        o.y = (xv[k].y + pv.y) * 0.125f;
        o.z = (xv[k].z + pv.z) * 0.125f;
        o.w = (xv[k].w + pv.w) * 0.125f;
        __stcs(&out[i], o);
    }
}

// ---------------------------------------------------------------------------
extern "C" void kernel_launch(void* const* d_in, const int* in_sizes, int n_in,
                              void* d_out, int out_size) {
    const float4* x = (const float4*)d_in[0];
    float4* out = (float4*)d_out;

    // A: warp-per-block sums (32768 blocks / 8 warps per CTA)
    block8_sum_kernel<<<BATCH * NBLK / 8, 256>>>(x);

    // B: fused pyramid (static smem only, <48KB)
    pyramid_kernel<<<BATCH * C4, 256>>>();

    // C: elementwise combine, 8 float4 per thread
    const int n4 = out_size / 4;                    // 16,777,216
    combine_kernel<<<n4 / (256 * C_UNROLL), 256>>>(x, out);
}